// round 14
// baseline (speedup 1.0000x reference)
#include <cuda_runtime.h>
#include <cuda_fp16.h>
#include <cstdint>

#define BB 4
#define SS 4096
#define DD 2048
#define DHALF 1024
#define MTOK (BB * SS)          // 16384
#define STRIDE_T (SS + 1)       // 4097
#define MVAL (BB * STRIDE_T)    // 16388
#define NMBLK 128               // 128-row blocks over MTOK
#define NPBLK 129               // 128-row blocks over MVAL (last partial)

// ---------------- scratch ----------------
__device__ __half g_xe  [(size_t)MVAL * DD];
__device__ __half g_w1t0[(size_t)DHALF * DD];
__device__ __half g_w1t1[(size_t)DHALF * DD];
__device__ __half g_w2t0[(size_t)DD * DHALF];
__device__ __half g_w2t1[(size_t)DD * DHALF];
__device__ __half g_o1  [(size_t)MVAL * DHALF];
__device__ __half g_y   [(size_t)MTOK * DD];    // pre-norm y (fp16)
__device__ float  g_sink[BB * DD];
__device__ int    g_cnt [NMBLK];                // gemm1 row-block completion (8)
__device__ int    g_cnt2[NMBLK];                // gemm2 row-block completion (16)
__device__ int    g_pk  [NPBLK];                // pack_x row-block completion (1)

// ---------------- helpers ----------------
__device__ __forceinline__ void cp16(uint32_t dst, const void* src) {
    asm volatile("cp.async.cg.shared.global [%0], [%1], 16;" :: "r"(dst), "l"(src));
}
__device__ __forceinline__ void ldm_x4(uint32_t a, uint32_t* r) {
    asm volatile("ldmatrix.sync.aligned.m8n8.x4.shared.b16 {%0,%1,%2,%3}, [%4];"
                 : "=r"(r[0]), "=r"(r[1]), "=r"(r[2]), "=r"(r[3]) : "r"(a));
}
__device__ __forceinline__ void mma16816(float* c, const uint32_t* a, uint32_t b0, uint32_t b1) {
    asm volatile(
        "mma.sync.aligned.m16n8k16.row.col.f32.f16.f16.f32 "
        "{%0,%1,%2,%3}, {%4,%5,%6,%7}, {%8,%9}, {%0,%1,%2,%3};"
        : "+f"(c[0]), "+f"(c[1]), "+f"(c[2]), "+f"(c[3])
        : "r"(a[0]), "r"(a[1]), "r"(a[2]), "r"(a[3]), "r"(b0), "r"(b1));
}
__device__ __forceinline__ uint32_t pack2h(float a, float b) {
    __half2 h = __floats2half2_rn(a, b);
    return *(uint32_t*)&h;
}

// ---------------- megakernel: pack_x + conv1 + conv2 + rmsnorm ------------
// GEMM tiles: 128 tokens x 128 outs, 8 warps (2x4), warp 64x32, BKC=64,
// 2-stage cp.async, 2 CTAs/SM.  (R9 operating point, unchanged)
// Schedule (3330 CTAs), all deps at strictly smaller bids:
//   [0, 129)        pack_x tile pb = bid (dependency-free)
//   [129, 513)      gemm1 lead  m = gbid/8, n = gbid%8     (waits g_pk)
//   [513, 2433)     80 groups of 24: 8x g1 (m=48+g) + 16x g2 (m=g)
//   [2433, 3201)    gemm2 tail  m = 80 + r/16, n = r%16    (waits g_cnt)
//   [3201, 3329)    rmsnorm tile mblk = bid-3201           (waits g_cnt2)
//   3329            lf1 writeback (independent)
#define BKC   64
#define AT_B  (130 * 128)
#define BT_B  (128 * BKC * 2)
#define STG_B (AT_B + 2 * BT_B)    // 49408
#define SMEM_DYN (2 * STG_B)       // 98816 -> 2 CTAs/SM

__global__ __launch_bounds__(256, 2)
void conv_dual(__half* __restrict__ xe,
               const float* __restrict__ xf, const float* __restrict__ lf1c,
               const __half* __restrict__ w1t0, const __half* __restrict__ w1t1,
               const __half* __restrict__ w2t0, const __half* __restrict__ w2t1,
               const float* __restrict__ b1, const float* __restrict__ b2,
               __half* __restrict__ o1, __half* __restrict__ y,
               float* __restrict__ lf2_out,
               const float* __restrict__ lnw, float* __restrict__ out,
               float* __restrict__ lf1_out)
{
    const int tid = threadIdx.x;
    const int wid = tid >> 5, lane = tid & 31;
    const int bid = blockIdx.x;

    // ---------------- pack_x lead tiles ----------------
    if (bid < NPBLK) {
        const int pb = bid;
        const int e = tid * 8;
        for (int lr = 0; lr < 128; lr++) {
            const int r = pb * 128 + lr;
            if (r >= MVAL) break;
            const int bb = r / STRIDE_T, ii = r % STRIDE_T;
            const float* src = (ii == 0) ? (lf1c + (size_t)bb * DD + e)
                                         : (xf + ((size_t)bb * SS + (ii - 1)) * DD + e);
            float4 v0 = ((const float4*)src)[0], v1 = ((const float4*)src)[1];
            uint4 u;
            u.x = pack2h(v0.x, v0.y); u.y = pack2h(v0.z, v0.w);
            u.z = pack2h(v1.x, v1.y); u.w = pack2h(v1.z, v1.w);
            *(uint4*)(xe + (size_t)r * DD + e) = u;
        }
        __threadfence();
        __syncthreads();
        if (tid == 0) atomicAdd(&g_pk[pb], 1);
        return;
    }

    // ---------------- tail tiles ----------------
    if (bid >= 3329) {            // lf1 writeback (independent)
        for (int i = tid; i < BB * DD; i += 256) {
            int b = i / DD, d = i % DD;
            lf1_out[i] = xf[((size_t)b * SS + SS - 1) * DD + d];
        }
        return;
    }
    if (bid >= 3201) {            // rmsnorm tile: 128 rows, warp-per-row
        const int mblk = bid - 3201;
        volatile int* vc2 = g_cnt2;
        while (vc2[mblk] < 16) __nanosleep(256);
        __threadfence();
        const int g0r = mblk * 128;
        for (int pass = 0; pass < 16; pass++) {
            const int g = g0r + pass * 8 + wid;
            const uint4* row = (const uint4*)(y + (size_t)g * DD);   // 256 uint4/row
            uint4 v[8];
            float s = 0.f;
            #pragma unroll
            for (int q = 0; q < 8; q++) {
                v[q] = row[lane + q * 32];
                float2 f0 = __half22float2(*(__half2*)&v[q].x);
                float2 f1 = __half22float2(*(__half2*)&v[q].y);
                float2 f2 = __half22float2(*(__half2*)&v[q].z);
                float2 f3 = __half22float2(*(__half2*)&v[q].w);
                s += f0.x*f0.x + f0.y*f0.y + f1.x*f1.x + f1.y*f1.y
                   + f2.x*f2.x + f2.y*f2.y + f3.x*f3.x + f3.y*f3.y;
            }
            #pragma unroll
            for (int o = 16; o; o >>= 1) s += __shfl_xor_sync(0xffffffffu, s, o);
            const float inv = rsqrtf(s * (1.0f / DD) + 1e-6f);
            float4* orow = (float4*)(out + (size_t)g * DD);          // 512 float4/row
            const float4* wrow = (const float4*)lnw;
            #pragma unroll
            for (int q = 0; q < 8; q++) {
                const int base = (lane + q * 32) * 2;
                float2 f0 = __half22float2(*(__half2*)&v[q].x);
                float2 f1 = __half22float2(*(__half2*)&v[q].y);
                float2 f2 = __half22float2(*(__half2*)&v[q].z);
                float2 f3 = __half22float2(*(__half2*)&v[q].w);
                float4 w0 = wrow[base], w1v = wrow[base + 1];
                orow[base]     = make_float4(f0.x*inv*w0.x, f0.y*inv*w0.y,
                                             f1.x*inv*w0.z, f1.y*inv*w0.w);
                orow[base + 1] = make_float4(f2.x*inv*w1v.x, f2.y*inv*w1v.y,
                                             f3.x*inv*w1v.z, f3.y*inv*w1v.w);
            }
        }
        return;
    }

    // ---------------- GEMM tiles ----------------
    const int gbid = bid - NPBLK;
    bool g1;
    int mblk, nblk;
    if (gbid < 384) { g1 = true; mblk = gbid >> 3; nblk = gbid & 7; }
    else if (gbid < 2304) {
        int r = gbid - 384, g = r / 24, j = r % 24;
        if (j < 8) { g1 = true;  mblk = 48 + g; nblk = j; }
        else       { g1 = false; mblk = g;      nblk = j - 8; }
    } else {
        int r = gbid - 2304;
        g1 = false; mblk = 80 + (r >> 4); nblk = r & 15;
    }

    const int KTOT = g1 ? DD : DHALF;
    const int KCH  = KTOT / BKC;
    const __half* A  = g1 ? xe   : o1;
    const __half* B0 = g1 ? w1t0 : w2t0;
    const __half* B1 = g1 ? w1t1 : w2t1;
    const float* biasv = g1 ? b1 : b2;

    const int g0 = mblk * 128;
    const int n0 = nblk * 128;
    const int b  = g0 >> 12;
    const int t0 = g0 & 4095;
    const size_t arow = (size_t)b * STRIDE_T + t0;

    extern __shared__ char smem_raw[];
    const uint32_t sbase = (uint32_t)__cvta_generic_to_shared(smem_raw);
    const int wm = wid >> 2, wn = wid & 3;

    auto load_a = [&](uint32_t dst, int kc) {
        const __half* src = A + arow * KTOT + kc;
        for (int idx = tid; idx < 129 * 8; idx += 256) {
            int r = idx >> 3, c = idx & 7;
            cp16(dst + (uint32_t)(r * 128 + ((c ^ (r & 7)) * 16)),
                 src + (size_t)r * KTOT + c * 8);
        }
    };
    auto load_b = [&](uint32_t dst, const __half* base, int kc) {
        const __half* src = base + (size_t)n0 * KTOT + kc;
        #pragma unroll
        for (int u = 0; u < 4; u++) {
            int idx = u * 256 + tid;
            int r = idx >> 3, c = idx & 7;
            cp16(dst + (uint32_t)(r * 128 + ((c ^ (r & 7)) * 16)),
                 src + (size_t)r * KTOT + c * 8);
        }
    };
    auto load_chunk = [&](int ch, int s) {
        const int kc = ch * BKC;
        const uint32_t st = sbase + s * STG_B;
        load_a(st, kc);
        load_b(st + AT_B, B0, kc);
        load_b(st + AT_B + BT_B, B1, kc);
        asm volatile("cp.async.commit_group;" ::: "memory");
    };

    // prefetch dependency-free B tiles of chunk 0, then resolve deps
    load_b(sbase + AT_B, B0, 0);
    load_b(sbase + AT_B + BT_B, B1, 0);
    asm volatile("cp.async.commit_group;" ::: "memory");

    if (g1) {
        const int pb0 = (int)(arow >> 7);
        const int pb1 = (int)((arow + 128) >> 7);
        volatile int* vp = g_pk;
        while (vp[pb0] == 0 || vp[pb1] == 0) __nanosleep(128);
        __threadfence();
    } else {
        volatile int* vc = g_cnt;
        const int mprev = (t0 > 0) ? mblk - 1 : mblk;
        while (vc[mblk] < 8 || vc[mprev] < 8) __nanosleep(128);
        __threadfence();
    }
    load_a(sbase, 0);
    asm volatile("cp.async.commit_group;" ::: "memory");

    float acc[4][4][4];
    #pragma unroll
    for (int i = 0; i < 4; i++)
        #pragma unroll
        for (int j = 0; j < 4; j++)
            #pragma unroll
            for (int q = 0; q < 4; q++) acc[i][j][q] = 0.f;

    const int ra = wm * 64 + (lane & 15);
    const int rb = wn * 32 + (lane & 15);
    const int chi = lane >> 4;

    for (int ch = 0; ch < KCH; ch++) {
        const int s = ch & 1;
        asm volatile("cp.async.wait_group 0;" ::: "memory");
        __syncthreads();
        if (ch + 1 < KCH) load_chunk(ch + 1, s ^ 1);

        const uint32_t st = sbase + s * STG_B;
        #pragma unroll
        for (int s16 = 0; s16 < BKC / 16; s16++) {
            const int c = s16 * 2 + chi;
            uint32_t bf[2][4];
            // tap 0: prev-token A rows x B0
            #pragma unroll
            for (int nf = 0; nf < 2; nf++) {
                const int r = rb + nf * 16;
                ldm_x4(st + AT_B + (uint32_t)(r * 128 + ((c ^ (r & 7)) * 16)), bf[nf]);
            }
            #pragma unroll
            for (int mi = 0; mi < 4; mi++) {
                uint32_t af[4];
                const int rp = ra + mi * 16;
                ldm_x4(st + (uint32_t)(rp * 128 + ((c ^ (rp & 7)) * 16)), af);
                #pragma unroll
                for (int ni = 0; ni < 4; ni++) {
                    const int nf = ni >> 1, p = ni & 1;
                    mma16816(acc[mi][ni], af, bf[nf][p], bf[nf][p + 2]);
                }
            }
            // tap 1: cur-token A rows (prev+1) x B1
            #pragma unroll
            for (int nf = 0; nf < 2; nf++) {
                const int r = rb + nf * 16;
                ldm_x4(st + AT_B + BT_B + (uint32_t)(r * 128 + ((c ^ (r & 7)) * 16)), bf[nf]);
            }
            #pragma unroll
            for (int mi = 0; mi < 4; mi++) {
                uint32_t af[4];
                const int rc = ra + mi * 16 + 1;
                ldm_x4(st + (uint32_t)(rc * 128 + ((c ^ (rc & 7)) * 16)), af);
                #pragma unroll
                for (int ni = 0; ni < 4; ni++) {
                    const int nf = ni >> 1, p = ni & 1;
                    mma16816(acc[mi][ni], af, bf[nf][p], bf[nf][p + 2]);
                }
            }
        }
    }

    // ---- fused epilogue ----
    const int er = lane >> 2, ec = (lane & 3) * 2;
    #pragma unroll
    for (int mi = 0; mi < 4; mi++) {
        const int lr0 = wm * 64 + mi * 16 + er;
        #pragma unroll
        for (int ni = 0; ni < 4; ni++) {
            const int gc = n0 + wn * 32 + ni * 8 + ec;
            const float bv0 = biasv[gc], bv1 = biasv[gc + 1];
            #pragma unroll
            for (int h = 0; h < 2; h++) {
                const int lr = lr0 + h * 8;
                float v0 = acc[mi][ni][h * 2 + 0] + bv0;
                float v1 = acc[mi][ni][h * 2 + 1] + bv1;
                if (g1) {
                    const size_t orow = arow + lr + 1;
                    *(uint32_t*)(o1 + orow * DHALF + gc) = pack2h(v0, v1);
                    if (t0 + lr == SS - 1) {
                        lf2_out[(size_t)b * DHALF + gc]     = v0;
                        lf2_out[(size_t)b * DHALF + gc + 1] = v1;
                    }
                } else {
                    const size_t g = (size_t)(g0 + lr);
                    const float2 xr = *(const float2*)(xf + g * DD + gc);
                    *(uint32_t*)(y + g * DD + gc) = pack2h(v0 + xr.x, v1 + xr.y);
                }
            }
        }
    }

    __threadfence();
    __syncthreads();
    if (tid == 0) atomicAdd(g1 ? &g_cnt[mblk] : &g_cnt2[mblk], 1);
}

// ---------------- weight pack (w1 + w2 in one launch) ----------------
__global__ __launch_bounds__(256)
void pack_w_all(const float* __restrict__ w1, const float* __restrict__ w2,
                __half* __restrict__ w1t0, __half* __restrict__ w1t1,
                __half* __restrict__ w2t0, __half* __restrict__ w2t1)
{
    int n = blockIdx.x;
    const float* w;
    __half *h0, *h1;
    int K;
    if (n < DHALF) { w = w1; h0 = w1t0; h1 = w1t1; K = DD; }
    else { n -= DHALF; w = w2; h0 = w2t0; h1 = w2t1; K = DHALF; }
    for (int k = threadIdx.x * 4; k < K; k += 256 * 4) {
        const float2* src = (const float2*)w + (size_t)n * K + k;
        float2 a = src[0], bq = src[1], c = src[2], d = src[3];
        uint2 u0, u1;
        u0.x = pack2h(a.x, bq.x); u0.y = pack2h(c.x, d.x);
        u1.x = pack2h(a.y, bq.y); u1.y = pack2h(c.y, d.y);
        *(uint2*)(h0 + (size_t)n * K + k) = u0;
        *(uint2*)(h1 + (size_t)n * K + k) = u1;
    }
}

// o1 cache rows + zero all counter arrays
__global__ __launch_bounds__(128)
void o1_cache(const float* __restrict__ lf2c, __half* __restrict__ oh)
{
    const int b = blockIdx.x, e = threadIdx.x * 8;
    const float4* src = (const float4*)(lf2c + (size_t)b * DHALF + e);
    float4 v0 = src[0], v1 = src[1];
    uint4 u;
    u.x = pack2h(v0.x, v0.y); u.y = pack2h(v0.z, v0.w);
    u.z = pack2h(v1.x, v1.y); u.w = pack2h(v1.z, v1.w);
    *(uint4*)(oh + (size_t)b * STRIDE_T * DHALF + e) = u;
    if (b == 0) {
        g_cnt[threadIdx.x] = 0;
        g_cnt2[threadIdx.x] = 0;
        g_pk[threadIdx.x] = 0;
        if (threadIdx.x == 0) g_pk[128] = 0;
    }
}

extern "C" void kernel_launch(void* const* d_in, const int* in_sizes, int n_in,
                              void* d_out, int out_size)
{
    const float* x    = (const float*)d_in[0];
    const float* lf1c = (const float*)d_in[1];
    const float* lf2c = (const float*)d_in[2];
    const float* w1   = (const float*)d_in[3];
    const float* b1   = (const float*)d_in[4];
    const float* w2   = (const float*)d_in[5];
    const float* b2   = (const float*)d_in[6];
    const float* lnw  = (const float*)d_in[7];
    float* out = (float*)d_out;

    __half *xh, *w1t0, *w1t1, *w2t0, *w2t1, *oh, *y;
    float *sink;
    cudaGetSymbolAddress((void**)&xh,   g_xe);
    cudaGetSymbolAddress((void**)&w1t0, g_w1t0);
    cudaGetSymbolAddress((void**)&w1t1, g_w1t1);
    cudaGetSymbolAddress((void**)&w2t0, g_w2t0);
    cudaGetSymbolAddress((void**)&w2t1, g_w2t1);
    cudaGetSymbolAddress((void**)&oh,   g_o1);
    cudaGetSymbolAddress((void**)&y,    g_y);
    cudaGetSymbolAddress((void**)&sink, g_sink);

    cudaFuncSetAttribute(conv_dual,
                         cudaFuncAttributeMaxDynamicSharedMemorySize, SMEM_DYN);

    const long long main_sz = (long long)MTOK * DD;
    const bool carry = (long long)out_size >= main_sz + BB * DD + BB * DHALF;
    float* lf1_out = carry ? out + main_sz : sink;
    float* lf2_out = carry ? out + main_sz + BB * DD : sink;

    pack_w_all<<<DHALF + DD, 256>>>(w1, w2, w1t0, w1t1, w2t0, w2t1);
    o1_cache<<<BB, 128>>>(lf2c, oh);

    // megakernel: pack_x + conv1 + conv2 + rmsnorm + lf1 (3330 tiles)
    conv_dual<<<3330, 256, SMEM_DYN>>>(xh, x, lf1c,
                                       w1t0, w1t1, w2t0, w2t1,
                                       b1, b2, oh, y, lf2_out,
                                       lnw, out, lf1_out);
}

// round 15
// speedup vs baseline: 1.0421x; 1.0421x over previous
#include <cuda_runtime.h>
#include <cuda_fp16.h>
#include <cstdint>

#define BB 4
#define SS 4096
#define DD 2048
#define DHALF 1024
#define MTOK (BB * SS)          // 16384
#define STRIDE_T (SS + 1)       // 4097
#define MVAL (BB * STRIDE_T)    // 16388
#define NMBLK 128               // 128-row blocks over MTOK

// ---------------- scratch ----------------
__device__ __half g_xe  [(size_t)MVAL * DD];
__device__ __half g_w1t0[(size_t)DHALF * DD];
__device__ __half g_w1t1[(size_t)DHALF * DD];
__device__ __half g_w2t0[(size_t)DD * DHALF];
__device__ __half g_w2t1[(size_t)DD * DHALF];
__device__ __half g_o1  [(size_t)MVAL * DHALF];
__device__ __half g_y   [(size_t)MTOK * DD];    // pre-norm y (fp16)
__device__ float  g_sink[BB * DD];
__device__ int    g_cnt [NMBLK];                // gemm1 row-block completion (8 n-tiles)

// ---------------- helpers ----------------
__device__ __forceinline__ void cp16(uint32_t dst, const void* src) {
    asm volatile("cp.async.cg.shared.global [%0], [%1], 16;" :: "r"(dst), "l"(src));
}
__device__ __forceinline__ void ldm_x4(uint32_t a, uint32_t* r) {
    asm volatile("ldmatrix.sync.aligned.m8n8.x4.shared.b16 {%0,%1,%2,%3}, [%4];"
                 : "=r"(r[0]), "=r"(r[1]), "=r"(r[2]), "=r"(r[3]) : "r"(a));
}
__device__ __forceinline__ void mma16816(float* c, const uint32_t* a, uint32_t b0, uint32_t b1) {
    asm volatile(
        "mma.sync.aligned.m16n8k16.row.col.f32.f16.f16.f32 "
        "{%0,%1,%2,%3}, {%4,%5,%6,%7}, {%8,%9}, {%0,%1,%2,%3};"
        : "+f"(c[0]), "+f"(c[1]), "+f"(c[2]), "+f"(c[3])
        : "r"(a[0]), "r"(a[1]), "r"(a[2]), "r"(a[3]), "r"(b0), "r"(b1));
}
__device__ __forceinline__ uint32_t pack2h(float a, float b) {
    __half2 h = __floats2half2_rn(a, b);
    return *(uint32_t*)&h;
}

// ---------------- merged dual-tap conv-GEMM (R9 operating point) ----------
// CTA tile: 128 tokens x 128 outs, 8 warps (2x4), warp 64x32, BKC=64,
// 2-stage cp.async, 2 CTAs/SM.
// Schedule (3072 CTAs):
//   bid <  384          : gemm1 (m = bid/8, n = bid%8)      m 0..47
//   384 <= bid < 2304   : 80 groups of 24: 8x g1 (m=48+g) + 16x g2 (m=g)
//   bid >= 2304         : gemm2 m = 80 + r/16, n = r%16
#define BKC   64
#define AT_B  (130 * 128)
#define BT_B  (128 * BKC * 2)
#define STG_B (AT_B + 2 * BT_B)    // 49408
#define SMEM_DYN (2 * STG_B)       // 98816 -> 2 CTAs/SM

__global__ __launch_bounds__(256, 2)
void conv_dual(const __half* __restrict__ xe,
               const __half* __restrict__ w1t0, const __half* __restrict__ w1t1,
               const __half* __restrict__ w2t0, const __half* __restrict__ w2t1,
               const float* __restrict__ b1, const float* __restrict__ b2,
               const float* __restrict__ xres,
               __half* __restrict__ o1, __half* __restrict__ y,
               float* __restrict__ lf2_out)
{
    // ---- decode schedule ----
    int bid = blockIdx.x;
    bool g1;
    int mblk, nblk;
    if (bid < 384) { g1 = true; mblk = bid >> 3; nblk = bid & 7; }
    else if (bid < 2304) {
        int r = bid - 384, g = r / 24, j = r % 24;
        if (j < 8) { g1 = true;  mblk = 48 + g; nblk = j; }
        else       { g1 = false; mblk = g;      nblk = j - 8; }
    } else {
        int r = bid - 2304;
        g1 = false; mblk = 80 + (r >> 4); nblk = r & 15;
    }

    const int KTOT = g1 ? DD : DHALF;
    const int KCH  = KTOT / BKC;
    const __half* A  = g1 ? xe   : o1;
    const __half* B0 = g1 ? w1t0 : w2t0;
    const __half* B1 = g1 ? w1t1 : w2t1;
    const float* biasv = g1 ? b1 : b2;

    const int g0 = mblk * 128;
    const int n0 = nblk * 128;
    const int b  = g0 >> 12;
    const int t0 = g0 & 4095;
    const size_t arow = (size_t)b * STRIDE_T + t0;

    extern __shared__ char smem_raw[];
    const uint32_t sbase = (uint32_t)__cvta_generic_to_shared(smem_raw);
    const int tid = threadIdx.x;
    const int wid = tid >> 5, lane = tid & 31;
    const int wm = wid >> 2, wn = wid & 3;

    auto load_a = [&](uint32_t dst, int kc) {
        const __half* src = A + arow * KTOT + kc;
        for (int idx = tid; idx < 129 * 8; idx += 256) {
            int r = idx >> 3, c = idx & 7;
            cp16(dst + (uint32_t)(r * 128 + ((c ^ (r & 7)) * 16)),
                 src + (size_t)r * KTOT + c * 8);
        }
    };
    auto load_b = [&](uint32_t dst, const __half* base, int kc) {
        const __half* src = base + (size_t)n0 * KTOT + kc;
        #pragma unroll
        for (int u = 0; u < 4; u++) {
            int idx = u * 256 + tid;
            int r = idx >> 3, c = idx & 7;
            cp16(dst + (uint32_t)(r * 128 + ((c ^ (r & 7)) * 16)),
                 src + (size_t)r * KTOT + c * 8);
        }
    };
    auto load_chunk = [&](int ch, int s) {
        const int kc = ch * BKC;
        const uint32_t st = sbase + s * STG_B;
        load_a(st, kc);
        load_b(st + AT_B, B0, kc);
        load_b(st + AT_B + BT_B, B1, kc);
        asm volatile("cp.async.commit_group;" ::: "memory");
    };

    // prefetch dependency-free B tiles of chunk 0, then resolve deps
    load_b(sbase + AT_B, B0, 0);
    load_b(sbase + AT_B + BT_B, B1, 0);
    asm volatile("cp.async.commit_group;" ::: "memory");

    if (!g1) {
        volatile int* vc = g_cnt;
        const int mprev = (t0 > 0) ? mblk - 1 : mblk;
        while (vc[mblk] < 8 || vc[mprev] < 8) __nanosleep(128);
        __threadfence();
    }
    load_a(sbase, 0);
    asm volatile("cp.async.commit_group;" ::: "memory");

    float acc[4][4][4];
    #pragma unroll
    for (int i = 0; i < 4; i++)
        #pragma unroll
        for (int j = 0; j < 4; j++)
            #pragma unroll
            for (int q = 0; q < 4; q++) acc[i][j][q] = 0.f;

    const int ra = wm * 64 + (lane & 15);
    const int rb = wn * 32 + (lane & 15);
    const int chi = lane >> 4;

    for (int ch = 0; ch < KCH; ch++) {
        const int s = ch & 1;
        asm volatile("cp.async.wait_group 0;" ::: "memory");
        __syncthreads();
        if (ch + 1 < KCH) load_chunk(ch + 1, s ^ 1);

        const uint32_t st = sbase + s * STG_B;
        #pragma unroll
        for (int s16 = 0; s16 < BKC / 16; s16++) {
            const int c = s16 * 2 + chi;
            uint32_t bf[2][4];
            // tap 0: prev-token A rows x B0
            #pragma unroll
            for (int nf = 0; nf < 2; nf++) {
                const int r = rb + nf * 16;
                ldm_x4(st + AT_B + (uint32_t)(r * 128 + ((c ^ (r & 7)) * 16)), bf[nf]);
            }
            #pragma unroll
            for (int mi = 0; mi < 4; mi++) {
                uint32_t af[4];
                const int rp = ra + mi * 16;
                ldm_x4(st + (uint32_t)(rp * 128 + ((c ^ (rp & 7)) * 16)), af);
                #pragma unroll
                for (int ni = 0; ni < 4; ni++) {
                    const int nf = ni >> 1, p = ni & 1;
                    mma16816(acc[mi][ni], af, bf[nf][p], bf[nf][p + 2]);
                }
            }
            // tap 1: cur-token A rows (prev+1) x B1
            #pragma unroll
            for (int nf = 0; nf < 2; nf++) {
                const int r = rb + nf * 16;
                ldm_x4(st + AT_B + BT_B + (uint32_t)(r * 128 + ((c ^ (r & 7)) * 16)), bf[nf]);
            }
            #pragma unroll
            for (int mi = 0; mi < 4; mi++) {
                uint32_t af[4];
                const int rc = ra + mi * 16 + 1;
                ldm_x4(st + (uint32_t)(rc * 128 + ((c ^ (rc & 7)) * 16)), af);
                #pragma unroll
                for (int ni = 0; ni < 4; ni++) {
                    const int nf = ni >> 1, p = ni & 1;
                    mma16816(acc[mi][ni], af, bf[nf][p], bf[nf][p + 2]);
                }
            }
        }
    }

    // ---- fused epilogue ----
    const int er = lane >> 2, ec = (lane & 3) * 2;
    #pragma unroll
    for (int mi = 0; mi < 4; mi++) {
        const int lr0 = wm * 64 + mi * 16 + er;
        #pragma unroll
        for (int ni = 0; ni < 4; ni++) {
            const int gc = n0 + wn * 32 + ni * 8 + ec;
            const float bv0 = biasv[gc], bv1 = biasv[gc + 1];
            #pragma unroll
            for (int h = 0; h < 2; h++) {
                const int lr = lr0 + h * 8;
                float v0 = acc[mi][ni][h * 2 + 0] + bv0;
                float v1 = acc[mi][ni][h * 2 + 1] + bv1;
                if (g1) {
                    const size_t orow = arow + lr + 1;
                    *(uint32_t*)(o1 + orow * DHALF + gc) = pack2h(v0, v1);
                    if (t0 + lr == SS - 1) {
                        lf2_out[(size_t)b * DHALF + gc]     = v0;
                        lf2_out[(size_t)b * DHALF + gc + 1] = v1;
                    }
                } else {
                    const size_t g = (size_t)(g0 + lr);
                    const float2 xr = *(const float2*)(xres + g * DD + gc);
                    *(uint32_t*)(y + g * DD + gc) = pack2h(v0 + xr.x, v1 + xr.y);
                }
            }
        }
    }

    if (g1) {
        __threadfence();
        __syncthreads();
        if (tid == 0) atomicAdd(&g_cnt[mblk], 1);
    }
}

// ---------------- pack kernels (fully parallel, R9 style) ----------------
__global__ __launch_bounds__(256)
void pack_x(const float* __restrict__ x, const float* __restrict__ lf1c,
            __half* __restrict__ xh)
{
    const int r = blockIdx.x, e = threadIdx.x * 8;
    const int b = r / STRIDE_T, i = r % STRIDE_T;
    const float* src = (i == 0) ? (lf1c + (size_t)b * DD + e)
                                : (x + ((size_t)b * SS + (i - 1)) * DD + e);
    float4 v0 = ((const float4*)src)[0], v1 = ((const float4*)src)[1];
    uint4 u;
    u.x = pack2h(v0.x, v0.y); u.y = pack2h(v0.z, v0.w);
    u.z = pack2h(v1.x, v1.y); u.w = pack2h(v1.z, v1.w);
    *(uint4*)(xh + (size_t)r * DD + e) = u;
}

__global__ __launch_bounds__(256)
void pack_w_all(const float* __restrict__ w1, const float* __restrict__ w2,
                __half* __restrict__ w1t0, __half* __restrict__ w1t1,
                __half* __restrict__ w2t0, __half* __restrict__ w2t1)
{
    int n = blockIdx.x;
    const float* w;
    __half *h0, *h1;
    int K;
    if (n < DHALF) { w = w1; h0 = w1t0; h1 = w1t1; K = DD; }
    else { n -= DHALF; w = w2; h0 = w2t0; h1 = w2t1; K = DHALF; }
    for (int k = threadIdx.x * 4; k < K; k += 256 * 4) {
        const float2* src = (const float2*)w + (size_t)n * K + k;
        float2 a = src[0], bq = src[1], c = src[2], d = src[3];
        uint2 u0, u1;
        u0.x = pack2h(a.x, bq.x); u0.y = pack2h(c.x, d.x);
        u1.x = pack2h(a.y, bq.y); u1.y = pack2h(c.y, d.y);
        *(uint2*)(h0 + (size_t)n * K + k) = u0;
        *(uint2*)(h1 + (size_t)n * K + k) = u1;
    }
}

// o1 cache rows + zero the completion counters
__global__ __launch_bounds__(128)
void o1_cache(const float* __restrict__ lf2c, __half* __restrict__ oh)
{
    const int b = blockIdx.x, e = threadIdx.x * 8;
    const float4* src = (const float4*)(lf2c + (size_t)b * DHALF + e);
    float4 v0 = src[0], v1 = src[1];
    uint4 u;
    u.x = pack2h(v0.x, v0.y); u.y = pack2h(v0.z, v0.w);
    u.z = pack2h(v1.x, v1.y); u.w = pack2h(v1.z, v1.w);
    *(uint4*)(oh + (size_t)b * STRIDE_T * DHALF + e) = u;
    if (b == 0) g_cnt[threadIdx.x] = 0;
}

// ---------------- RMSNorm over fp16 y ----------------
__global__ __launch_bounds__(256)
void rmsnorm_kernel(const __half* __restrict__ y, const float* __restrict__ ln_w,
                    float* __restrict__ out)
{
    const int g = blockIdx.x;
    const uint4* row = (const uint4*)(y + (size_t)g * DD);   // 256 uint4/row
    uint4 v = row[threadIdx.x];                              // 8 halves
    float2 f0 = __half22float2(*(__half2*)&v.x);
    float2 f1 = __half22float2(*(__half2*)&v.y);
    float2 f2 = __half22float2(*(__half2*)&v.z);
    float2 f3 = __half22float2(*(__half2*)&v.w);
    float s = f0.x*f0.x + f0.y*f0.y + f1.x*f1.x + f1.y*f1.y
            + f2.x*f2.x + f2.y*f2.y + f3.x*f3.x + f3.y*f3.y;
    __shared__ float red[8];
    #pragma unroll
    for (int o = 16; o; o >>= 1) s += __shfl_down_sync(0xffffffffu, s, o);
    if ((threadIdx.x & 31) == 0) red[threadIdx.x >> 5] = s;
    __syncthreads();
    if (threadIdx.x < 32) {
        float t = (threadIdx.x < 8) ? red[threadIdx.x] : 0.f;
        #pragma unroll
        for (int o = 4; o; o >>= 1) t += __shfl_down_sync(0xffffffffu, t, o);
        if (threadIdx.x == 0) red[0] = t;
    }
    __syncthreads();
    const float inv = rsqrtf(red[0] * (1.0f / DD) + 1e-6f);
    float4* orow = (float4*)(out + (size_t)g * DD);
    const float4* wrow = (const float4*)ln_w;
    const int base = threadIdx.x * 2;
    float4 w0 = wrow[base], w1 = wrow[base + 1];
    orow[base]     = make_float4(f0.x*inv*w0.x, f0.y*inv*w0.y,
                                 f1.x*inv*w0.z, f1.y*inv*w0.w);
    orow[base + 1] = make_float4(f2.x*inv*w1.x, f2.y*inv*w1.y,
                                 f3.x*inv*w1.z, f3.y*inv*w1.w);
}

__global__ void write_lf1(const float* __restrict__ x, float* __restrict__ out_lf1)
{
    int i = blockIdx.x * blockDim.x + threadIdx.x;
    if (i < BB * DD) {
        int b = i / DD, d = i % DD;
        out_lf1[i] = x[((size_t)b * SS + SS - 1) * DD + d];
    }
}

extern "C" void kernel_launch(void* const* d_in, const int* in_sizes, int n_in,
                              void* d_out, int out_size)
{
    const float* x    = (const float*)d_in[0];
    const float* lf1c = (const float*)d_in[1];
    const float* lf2c = (const float*)d_in[2];
    const float* w1   = (const float*)d_in[3];
    const float* b1   = (const float*)d_in[4];
    const float* w2   = (const float*)d_in[5];
    const float* b2   = (const float*)d_in[6];
    const float* lnw  = (const float*)d_in[7];
    float* out = (float*)d_out;

    __half *xh, *w1t0, *w1t1, *w2t0, *w2t1, *oh, *y;
    float *sink;
    cudaGetSymbolAddress((void**)&xh,   g_xe);
    cudaGetSymbolAddress((void**)&w1t0, g_w1t0);
    cudaGetSymbolAddress((void**)&w1t1, g_w1t1);
    cudaGetSymbolAddress((void**)&w2t0, g_w2t0);
    cudaGetSymbolAddress((void**)&w2t1, g_w2t1);
    cudaGetSymbolAddress((void**)&oh,   g_o1);
    cudaGetSymbolAddress((void**)&y,    g_y);
    cudaGetSymbolAddress((void**)&sink, g_sink);

    cudaFuncSetAttribute(conv_dual,
                         cudaFuncAttributeMaxDynamicSharedMemorySize, SMEM_DYN);

    const long long main_sz = (long long)MTOK * DD;
    const bool carry = (long long)out_size >= main_sz + BB * DD + BB * DHALF;
    float* lf1_out = carry ? out + main_sz : sink;
    float* lf2_out = carry ? out + main_sz + BB * DD : sink;

    pack_x <<<MVAL, 256>>>(x, lf1c, xh);
    pack_w_all<<<DHALF + DD, 256>>>(w1, w2, w1t0, w1t1, w2t0, w2t1);
    o1_cache<<<BB, 128>>>(lf2c, oh);

    // merged conv1 + conv2 (3072 tiles, row-block dependency counters)
    conv_dual<<<3072, 256, SMEM_DYN>>>(xh, w1t0, w1t1, w2t0, w2t1,
                                       b1, b2, x, oh, y, lf2_out);

    rmsnorm_kernel<<<MTOK, 256>>>(y, lnw, out);
    if (carry) write_lf1<<<(BB * DD + 255) / 256, 256>>>(x, lf1_out);
}